// round 15
// baseline (speedup 1.0000x reference)
#include <cuda_runtime.h>
#include <cuda_bf16.h>

// Constants exactly as the fp32 reference stores them (promoted via float).
// DT_Q = DT/4 and ADV4 = 4*ADVECT are EXACT binary rescalings that cancel the
// 4x-scaled gradient accumulator produced by the doubled-root NR.
#define DT_Q   ((double)0.2f  * 0.25)
#define ADV4   ((double)0.05f * 4.0)
#define EPS_C  ((double)1e-4f)

#define C0 ((double)-2.25f)
#define C1 ((double)-0.75f)
#define C2 ((double) 0.75f)
#define C3 ((double) 2.25f)
// Half-mus: exact binary halving of the promoted fp32 values.
#define MH0 ((double)0.5f * 0.5)
#define MH1 ((double)0.3f * 0.5)
#define MH2 ((double)0.6f * 0.5)
#define MH3 ((double)0.4f * 0.5)

// fp64 rsqrt seed: MUFU.RSQ64H (~2^-21 rel err).
__device__ __forceinline__ double rsq_seed(double x)
{
    double y;
    asm("rsqrt.approx.ftz.f64 %0, %1;" : "=d"(y) : "d"(x));
    return y;
}

// fp64 reciprocal: MUFU.RCP64H seed + 1 Newton -> ~1e-12 rel err.
__device__ __forceinline__ double drcp(double x)
{
    double y;
    asm("rcp.approx.ftz.f64 %0, %1;" : "=d"(y) : "d"(x));
    double t = __fma_rn(-x, y, 2.0);
    return y * t;
}

// One (j,k) interaction, doubled-root NR, r2 fused as fma(dx,dx,ey):
//   yc  = y0*(3 - r2*y0^2)  -> 2/r  (~1e-12)
//   w   = (mu/2)*yc         -> mu/r  (exact)
//   m3p = w*yc^2            -> 4*mu/r^3  (cancelled by DT_Q in epilogue)
// 10 fp64 slots + MUFU — algebraic floor for this interaction.
__device__ __forceinline__ void interact(double ey,
                                         double dx, double dy, double muh,
                                         double& nn, double& gx, double& gy)
{
    double r2  = __fma_rn(dx, dx, ey);
    double y0  = rsq_seed(r2);
    double t   = r2 * y0;
    double c   = __fma_rn(-t, y0, 3.0);
    double yc  = y0 * c;           // 2/r
    double w   = muh * yc;         // mu/r
    nn += w;
    double i2p = yc * yc;          // 4/r^2
    double m3p = w * i2p;          // 4*mu/r^3
    gx = __fma_rn(-m3p, dx, gx);
    gy = __fma_rn(-m3p, dy, gy);
}

__global__ __launch_bounds__(256)
void pmflow_kernel(const float2* __restrict__ z,
                   float2* __restrict__ out,
                   int n)
{
    int i = blockIdx.x * blockDim.x + threadIdx.x;
    if (i >= n) return;

    float2 zp = z[i];
    double zx = (double)zp.x;
    double zy = (double)zp.y;

#pragma unroll
    for (int s = 0; s < 6; s++) {
        // Separable per-axis precompute (scalar, no local arrays).
        double dx0 = zx - C0, dx1 = zx - C1, dx2_ = zx - C2, dx3 = zx - C3;
        double dy0 = zy - C0, dy1 = zy - C1, dy2_ = zy - C2, dy3 = zy - C3;

        double ey0 = __fma_rn(dy0, dy0, EPS_C);
        double ey1 = __fma_rn(dy1, dy1, EPS_C);
        double ey2 = __fma_rn(dy2_, dy2_, EPS_C);
        double ey3 = __fma_rn(dy3, dy3, EPS_C);

        // Single accumulator chains: the 16 interactions provide abundant
        // independent work between consecutive uses of each accumulator.
        double nn = 1.0, gx = 0.0, gy = 0.0;

        interact(ey0, dx0, dy0, MH0, nn, gx, gy);
        interact(ey0, dx2_, dy0, MH0, nn, gx, gy);
        interact(ey1, dx0, dy1, MH1, nn, gx, gy);
        interact(ey1, dx2_, dy1, MH1, nn, gx, gy);
        interact(ey2, dx0, dy2_, MH2, nn, gx, gy);
        interact(ey2, dx2_, dy2_, MH2, nn, gx, gy);
        interact(ey3, dx0, dy3, MH3, nn, gx, gy);
        interact(ey3, dx2_, dy3, MH3, nn, gx, gy);

        interact(ey0, dx1, dy0, MH0, nn, gx, gy);
        interact(ey0, dx3, dy0, MH0, nn, gx, gy);
        interact(ey1, dx1, dy1, MH1, nn, gx, gy);
        interact(ey1, dx3, dy1, MH1, nn, gx, gy);
        interact(ey2, dx1, dy2_, MH2, nn, gx, gy);
        interact(ey2, dx3, dy2_, MH2, nn, gx, gy);
        interact(ey3, dx1, dy3, MH3, nn, gx, gy);
        interact(ey3, dx3, dy3, MH3, nn, gx, gy);

        double invn = drcp(nn);
        double gxi  = gx * invn;                // 4 * gx/n
        double a    = __fma_rn(gy, invn, ADV4); // 4 * (gy/n + ADVECT)
        zx = __fma_rn(DT_Q, gxi, zx);           // DT/4 cancels the 4 exactly
        zy = __fma_rn(DT_Q, a,   zy);
        zx = fmin(fmax(zx, -3.0), 3.0);
        zy = fmin(fmax(zy, -3.0), 3.0);
    }

    out[i] = make_float2((float)zx, (float)zy);
}

extern "C" void kernel_launch(void* const* d_in, const int* in_sizes, int n_in,
                              void* d_out, int out_size)
{
    const float2* z   = (const float2*)d_in[0];   // (B,2) float32
    float2*       out = (float2*)d_out;           // (B,2) float32

    int n = in_sizes[0] / 2;                      // B particles
    int threads = 256;
    int blocks  = (n + threads - 1) / threads;
    pmflow_kernel<<<blocks, threads>>>(z, out, n);
}

// round 16
// speedup vs baseline: 1.0627x; 1.0627x over previous
#include <cuda_runtime.h>
#include <cuda_bf16.h>

// Constants exactly as the fp32 reference stores them (promoted via float).
// DT_Q = DT/4 cancels the 4x-scaled gradient accumulators (q = (2/r)^3 = 8/r^3,
// muh = mu/2 -> muh*q = 4*mu/r^3). ADV4 = 4*ADVECT matches the scale.
#define DT_Q   ((double)0.2f  * 0.25)
#define ADV4   ((double)0.05f * 4.0)
#define EPS_C  ((double)1e-4f)

#define C0 ((double)-2.25f)
#define C1 ((double)-0.75f)
#define C2 ((double) 0.75f)
#define C3 ((double) 2.25f)
// Half-mus: exact binary halving of the promoted fp32 values.
#define MH0 ((double)0.5f * 0.5)
#define MH1 ((double)0.3f * 0.5)
#define MH2 ((double)0.6f * 0.5)
#define MH3 ((double)0.4f * 0.5)

// fp64 rsqrt seed: MUFU.RSQ64H (~2^-21 rel err).
__device__ __forceinline__ double rsq_seed(double x)
{
    double y;
    asm("rsqrt.approx.ftz.f64 %0, %1;" : "=d"(y) : "d"(x));
    return y;
}

// fp64 reciprocal: MUFU.RCP64H seed + 1 Newton -> ~1e-12 rel err.
__device__ __forceinline__ double drcp(double x)
{
    double y;
    asm("rcp.approx.ftz.f64 %0, %1;" : "=d"(y) : "d"(x));
    double t = __fma_rn(-x, y, 2.0);
    return y * t;
}

// NR core for one (j,k): r2 -> yc = 2/r (~1e-12) and q = yc^3 = 8/r^3.
// 6 fp64 slots + MUFU. All mu/dx/dy factors are hoisted into the step-level
// factored reductions.
__device__ __forceinline__ void ycq(double dx, double ey, double& yc, double& q)
{
    double r2  = __fma_rn(dx, dx, ey);
    double y0  = rsq_seed(r2);
    double t   = r2 * y0;
    double c   = __fma_rn(-t, y0, 3.0);
    yc = y0 * c;                   // 2/r
    double yc2 = yc * yc;          // 4/r^2
    q  = yc2 * yc;                 // 8/r^3
}

__global__ __launch_bounds__(256)
void pmflow_kernel(const float2* __restrict__ z,
                   float2* __restrict__ out,
                   int n)
{
    int i = blockIdx.x * blockDim.x + threadIdx.x;
    if (i >= n) return;

    float2 zp = z[i];
    double zx = (double)zp.x;
    double zy = (double)zp.y;

#pragma unroll
    for (int s = 0; s < 6; s++) {
        double dx0 = zx - C0, dx1 = zx - C1, dx2_ = zx - C2, dx3 = zx - C3;
        double dy0 = zy - C0, dy1 = zy - C1, dy2_ = zy - C2, dy3 = zy - C3;

        double ey0 = __fma_rn(dy0, dy0, EPS_C);
        double ey1 = __fma_rn(dy1, dy1, EPS_C);
        double ey2 = __fma_rn(dy2_, dy2_, EPS_C);
        double ey3 = __fma_rn(dy3, dy3, EPS_C);

        // (mu/2)*dy per k, hoisted out of the gy reduction.
        double mudy0 = MH0 * dy0, mudy1 = MH1 * dy1;
        double mudy2 = MH2 * dy2_, mudy3 = MH3 * dy3;

        double yc0, q0, yc1, q1, yc2v, q2, yc3, q3;

        // ---- j = 0 group: initializes syc_k, sq_k, gxs ----
        ycq(dx0, ey0, yc0, q0);
        ycq(dx0, ey1, yc1, q1);
        ycq(dx0, ey2, yc2v, q2);
        ycq(dx0, ey3, yc3, q3);
        double syc0 = yc0, syc1 = yc1, syc2 = yc2v, syc3 = yc3;
        double sq0 = q0, sq1 = q1, sq2 = q2, sq3 = q3;
        double sj  = __fma_rn(MH1, q1, __fma_rn(MH2, q2,
                     __fma_rn(MH3, q3, MH0 * q0)));
        double gxs = dx0 * sj;                 // positive 4x-scaled sum

        // ---- j = 1 group ----
        ycq(dx1, ey0, yc0, q0);
        ycq(dx1, ey1, yc1, q1);
        ycq(dx1, ey2, yc2v, q2);
        ycq(dx1, ey3, yc3, q3);
        syc0 += yc0; syc1 += yc1; syc2 += yc2v; syc3 += yc3;
        sq0 += q0; sq1 += q1; sq2 += q2; sq3 += q3;
        sj  = __fma_rn(MH1, q1, __fma_rn(MH2, q2,
              __fma_rn(MH3, q3, MH0 * q0)));
        gxs = __fma_rn(dx1, sj, gxs);

        // ---- j = 2 group ----
        ycq(dx2_, ey0, yc0, q0);
        ycq(dx2_, ey1, yc1, q1);
        ycq(dx2_, ey2, yc2v, q2);
        ycq(dx2_, ey3, yc3, q3);
        syc0 += yc0; syc1 += yc1; syc2 += yc2v; syc3 += yc3;
        sq0 += q0; sq1 += q1; sq2 += q2; sq3 += q3;
        sj  = __fma_rn(MH1, q1, __fma_rn(MH2, q2,
              __fma_rn(MH3, q3, MH0 * q0)));
        gxs = __fma_rn(dx2_, sj, gxs);

        // ---- j = 3 group ----
        ycq(dx3, ey0, yc0, q0);
        ycq(dx3, ey1, yc1, q1);
        ycq(dx3, ey2, yc2v, q2);
        ycq(dx3, ey3, yc3, q3);
        syc0 += yc0; syc1 += yc1; syc2 += yc2v; syc3 += yc3;
        sq0 += q0; sq1 += q1; sq2 += q2; sq3 += q3;
        sj  = __fma_rn(MH1, q1, __fma_rn(MH2, q2,
              __fma_rn(MH3, q3, MH0 * q0)));
        gxs = __fma_rn(dx3, sj, gxs);

        // n = 1 + Sum_k muh_k * (Sum_j yc_jk)   (muh hoisted: 4 fmas)
        double nn = __fma_rn(MH3, syc3, __fma_rn(MH2, syc2,
                    __fma_rn(MH1, syc1, __fma_rn(MH0, syc0, 1.0))));

        // gyP = Sum_k (muh_k*dy_k) * (Sum_j q_jk)  (positive 4x-scaled sum)
        double gyP = __fma_rn(mudy1, sq1, __fma_rn(mudy2, sq2,
                     __fma_rn(mudy3, sq3, mudy0 * sq0)));

        double invn = drcp(nn);
        double gxi  = gxs * invn;                 // 4 * (-gx)/n, sign below
        double a    = __fma_rn(-gyP, invn, ADV4); // 4 * (gy/n + ADVECT)
        zx = __fma_rn(-(DT_Q), gxi, zx);          // DT/4 cancels 4 exactly
        zy = __fma_rn(DT_Q, a, zy);
        zx = fmin(fmax(zx, -3.0), 3.0);
        zy = fmin(fmax(zy, -3.0), 3.0);
    }

    out[i] = make_float2((float)zx, (float)zy);
}

extern "C" void kernel_launch(void* const* d_in, const int* in_sizes, int n_in,
                              void* d_out, int out_size)
{
    const float2* z   = (const float2*)d_in[0];   // (B,2) float32
    float2*       out = (float2*)d_out;           // (B,2) float32

    int n = in_sizes[0] / 2;                      // B particles
    int threads = 256;
    int blocks  = (n + threads - 1) / threads;
    pmflow_kernel<<<blocks, threads>>>(z, out, n);
}

// round 17
// speedup vs baseline: 1.0640x; 1.0013x over previous
#include <cuda_runtime.h>
#include <cuda_bf16.h>

// Constants exactly as the fp32 reference stores them (promoted via float).
// DT_Q = DT/4 cancels the 4x-scaled gradient accumulators (q = (2/r)^3 = 8/r^3,
// muh = mu/2 -> muh*q = 4*mu/r^3). ADV4 = 4*ADVECT matches the scale.
#define DT_Q   ((double)0.2f  * 0.25)
#define ADV4   ((double)0.05f * 4.0)
#define EPS_C  ((double)1e-4f)

#define C0 ((double)-2.25f)
#define C1 ((double)-0.75f)
#define C2 ((double) 0.75f)
#define C3 ((double) 2.25f)
// Half-mus: exact binary halving of the promoted fp32 values.
#define MH0 ((double)0.5f * 0.5)
#define MH1 ((double)0.3f * 0.5)
#define MH2 ((double)0.6f * 0.5)
#define MH3 ((double)0.4f * 0.5)

// fp64 rsqrt seed: MUFU.RSQ64H (~2^-21 rel err).
__device__ __forceinline__ double rsq_seed(double x)
{
    double y;
    asm("rsqrt.approx.ftz.f64 %0, %1;" : "=d"(y) : "d"(x));
    return y;
}

// fp64 reciprocal: MUFU.RCP64H seed + 1 Newton -> ~1e-12 rel err.
__device__ __forceinline__ double drcp(double x)
{
    double y;
    asm("rcp.approx.ftz.f64 %0, %1;" : "=d"(y) : "d"(x));
    double t = __fma_rn(-x, y, 2.0);
    return y * t;
}

// NR core for one (j,k): r2 -> yc = 2/r (~1e-12) and q = yc^3 = 8/r^3.
// 6 fp64 slots + MUFU. All mu/dx/dy factors are hoisted into the step-level
// factored reductions.
__device__ __forceinline__ void ycq(double dx, double ey, double& yc, double& q)
{
    double r2  = __fma_rn(dx, dx, ey);
    double y0  = rsq_seed(r2);
    double t   = r2 * y0;
    double c   = __fma_rn(-t, y0, 3.0);
    yc = y0 * c;                   // 2/r
    double yc2 = yc * yc;          // 4/r^2
    q  = yc2 * yc;                 // 8/r^3
}

__global__ __launch_bounds__(256)
void pmflow_kernel(const float2* __restrict__ z,
                   float2* __restrict__ out,
                   int n)
{
    int i = blockIdx.x * blockDim.x + threadIdx.x;
    if (i >= n) return;

    float2 zp = z[i];
    double zx = (double)zp.x;
    double zy = (double)zp.y;

#pragma unroll
    for (int s = 0; s < 6; s++) {
        double dx0 = zx - C0, dx1 = zx - C1, dx2_ = zx - C2, dx3 = zx - C3;
        double dy0 = zy - C0, dy1 = zy - C1, dy2_ = zy - C2, dy3 = zy - C3;

        double ey0 = __fma_rn(dy0, dy0, EPS_C);
        double ey1 = __fma_rn(dy1, dy1, EPS_C);
        double ey2 = __fma_rn(dy2_, dy2_, EPS_C);
        double ey3 = __fma_rn(dy3, dy3, EPS_C);

        // (mu/2)*dy per k, hoisted out of the gy reduction.
        double mudy0 = MH0 * dy0, mudy1 = MH1 * dy1;
        double mudy2 = MH2 * dy2_, mudy3 = MH3 * dy3;

        double yc0, q0, yc1, q1, yc2v, q2, yc3, q3;

        // ---- j = 0 group: initializes syc_k, sq_k, gxs ----
        ycq(dx0, ey0, yc0, q0);
        ycq(dx0, ey1, yc1, q1);
        ycq(dx0, ey2, yc2v, q2);
        ycq(dx0, ey3, yc3, q3);
        double syc0 = yc0, syc1 = yc1, syc2 = yc2v, syc3 = yc3;
        double sq0 = q0, sq1 = q1, sq2 = q2, sq3 = q3;
        double sj  = __fma_rn(MH1, q1, __fma_rn(MH2, q2,
                     __fma_rn(MH3, q3, MH0 * q0)));
        double gxs = dx0 * sj;                 // positive 4x-scaled sum

        // ---- j = 1 group ----
        ycq(dx1, ey0, yc0, q0);
        ycq(dx1, ey1, yc1, q1);
        ycq(dx1, ey2, yc2v, q2);
        ycq(dx1, ey3, yc3, q3);
        syc0 += yc0; syc1 += yc1; syc2 += yc2v; syc3 += yc3;
        sq0 += q0; sq1 += q1; sq2 += q2; sq3 += q3;
        sj  = __fma_rn(MH1, q1, __fma_rn(MH2, q2,
              __fma_rn(MH3, q3, MH0 * q0)));
        gxs = __fma_rn(dx1, sj, gxs);

        // ---- j = 2 group ----
        ycq(dx2_, ey0, yc0, q0);
        ycq(dx2_, ey1, yc1, q1);
        ycq(dx2_, ey2, yc2v, q2);
        ycq(dx2_, ey3, yc3, q3);
        syc0 += yc0; syc1 += yc1; syc2 += yc2v; syc3 += yc3;
        sq0 += q0; sq1 += q1; sq2 += q2; sq3 += q3;
        sj  = __fma_rn(MH1, q1, __fma_rn(MH2, q2,
              __fma_rn(MH3, q3, MH0 * q0)));
        gxs = __fma_rn(dx2_, sj, gxs);

        // ---- j = 3 group ----
        ycq(dx3, ey0, yc0, q0);
        ycq(dx3, ey1, yc1, q1);
        ycq(dx3, ey2, yc2v, q2);
        ycq(dx3, ey3, yc3, q3);
        syc0 += yc0; syc1 += yc1; syc2 += yc2v; syc3 += yc3;
        sq0 += q0; sq1 += q1; sq2 += q2; sq3 += q3;
        sj  = __fma_rn(MH1, q1, __fma_rn(MH2, q2,
              __fma_rn(MH3, q3, MH0 * q0)));
        gxs = __fma_rn(dx3, sj, gxs);

        // n = 1 + Sum_k muh_k * (Sum_j yc_jk)   (muh hoisted: 4 fmas)
        double nn = __fma_rn(MH3, syc3, __fma_rn(MH2, syc2,
                    __fma_rn(MH1, syc1, __fma_rn(MH0, syc0, 1.0))));

        // gyP = Sum_k (muh_k*dy_k) * (Sum_j q_jk)  (positive 4x-scaled sum)
        double gyP = __fma_rn(mudy1, sq1, __fma_rn(mudy2, sq2,
                     __fma_rn(mudy3, sq3, mudy0 * sq0)));

        double invn = drcp(nn);
        double gxi  = gxs * invn;                 // 4 * (-gx)/n, sign below
        double a    = __fma_rn(-gyP, invn, ADV4); // 4 * (gy/n + ADVECT)
        zx = __fma_rn(-(DT_Q), gxi, zx);          // DT/4 cancels 4 exactly
        zy = __fma_rn(DT_Q, a, zy);
        zx = fmin(fmax(zx, -3.0), 3.0);
        zy = fmin(fmax(zy, -3.0), 3.0);
    }

    out[i] = make_float2((float)zx, (float)zy);
}

extern "C" void kernel_launch(void* const* d_in, const int* in_sizes, int n_in,
                              void* d_out, int out_size)
{
    const float2* z   = (const float2*)d_in[0];   // (B,2) float32
    float2*       out = (float2*)d_out;           // (B,2) float32

    int n = in_sizes[0] / 2;                      // B particles
    int threads = 256;
    int blocks  = (n + threads - 1) / threads;
    pmflow_kernel<<<blocks, threads>>>(z, out, n);
}